// round 15
// baseline (speedup 1.0000x reference)
#include <cuda_runtime.h>
#include <cuda_bf16.h>

#define TS       100
#define FDIM     64
#define HDIM     32
#define DEEP_N   3200            // TS * HDIM
#define WIDE_OFF 8150            // DEEP_N + NPAIR(4950)
#define NTHREADS 224
#define NWARPS   7
#define SPC      2               // samples per CTA

#define MT    7                  // m16 tiles covering 112 >= 100 rows
#define KT_FM 4                  // k16 tiles over f (Gram: k = feature dim)
#define NBLK  28                 // upper-tri 16x16 S-blocks (7*8/2)
#define KT_DP 4                  // k16 tiles covering 64 (deep)
#define NT_DP 4                  // n8 tiles covering 32 (deep)

#define EB_STRIDE 72             // halves per row; 144B -> conflict-free ldmatrix
#define SAMPLE_B  (112 * EB_STRIDE * 2)   // bytes per sample tile (16128)

// ---- batch-invariant fragment-major constants (rebuilt each launch) ----
__device__ uint4  g_wpairbf[NBLK * 32];          // pair weights, bf16, S C-frag layout
__device__ uint2  g_wdfrag[KT_DP * NT_DP * 32];  // w_deep bf16 b-frags
__device__ uint2  g_wffndbf[MT * NT_DP * 32];    // w_ffn(deep) bf16, deep C-frag layout
__device__ float2 g_bdfrag[NT_DP * 32];          // b_deep in deep C-frag layout
__device__ __align__(16) uint2 g_wwidebf[TS * FDIM / 4];  // wide weights bf16

// balanced fm schedule: 4 blocks per warp, grouped by A-row for cache reuse
__constant__ signed char BLK_MI[NWARPS][4] = {
    {0,0,0,0},{1,1,1,1},{2,2,2,2},{3,3,3,3},{4,4,4,0},{5,5,0,0},{6,1,1,2}};
__constant__ signed char BLK_MJ[NWARPS][4] = {
    {0,1,2,3},{1,2,3,4},{2,3,4,5},{3,4,5,6},{4,5,6,4},{5,6,5,6},{6,5,6,6}};
__constant__ signed char BLK_ID[NWARPS][4] = {
    {0,1,2,3},{7,8,9,10},{13,14,15,16},{18,19,20,21},{22,23,24,4},{25,26,5,6},{27,11,12,17}};

__device__ __forceinline__ unsigned pack_bf2(float lo, float hi) {
    __nv_bfloat162 h = __floats2bfloat162_rn(lo, hi);
    return *reinterpret_cast<unsigned*>(&h);
}
__device__ __forceinline__ float2 bf2f(unsigned u) {
    return __bfloat1622float2(*reinterpret_cast<__nv_bfloat162*>(&u));
}
__device__ __forceinline__ unsigned smem_u32(const void* p) {
    return (unsigned)__cvta_generic_to_shared(p);
}
__device__ __forceinline__ float pairw(const float* w_ffn, int t, int tp) {
    if (t < TS && tp < TS && t < tp)
        return w_ffn[DEEP_N + t * (2 * TS - t - 1) / 2 + (tp - t - 1)];
    return 0.f;
}

__global__ void build_consts(const float* __restrict__ w_deep,
                             const float* __restrict__ b_deep,
                             const float* __restrict__ w_ffn)
{
    const int tid  = blockIdx.x * blockDim.x + threadIdx.x;
    const int lane = tid & 31;

    // wide weights -> bf16 pairs (source is only float2-aligned)
    if (tid < TS * FDIM / 4) {
        const float2 a = *(const float2*)(w_ffn + WIDE_OFF + tid * 4);
        const float2 c = *(const float2*)(w_ffn + WIDE_OFF + tid * 4 + 2);
        g_wwidebf[tid] = make_uint2(pack_bf2(a.x, a.y), pack_bf2(c.x, c.y));
    }

    // pair-weight bf16 fragments for S = E E^T blocks (upper-tri, incl. diagonal)
    if (tid < NBLK * 32) {
        const int blk = tid >> 5;
        int mi = 0, rem = blk;
        while (rem >= MT - mi) { rem -= MT - mi; ++mi; }
        const int mj = mi + rem;
        const int t  = mi * 16 + (lane >> 2);
        const int tp = mj * 16 + (lane & 3) * 2;
        g_wpairbf[tid] = make_uint4(
            pack_bf2(pairw(w_ffn, t,     tp),     pairw(w_ffn, t,     tp + 1)),
            pack_bf2(pairw(w_ffn, t + 8, tp),     pairw(w_ffn, t + 8, tp + 1)),
            pack_bf2(pairw(w_ffn, t,     tp + 8), pairw(w_ffn, t,     tp + 9)),
            pack_bf2(pairw(w_ffn, t + 8, tp + 8), pairw(w_ffn, t + 8, tp + 9)));
    }

    // w_deep b-fragments
    if (tid < KT_DP * NT_DP * 32) {
        const int n = (tid >> 5) & 3;
        const int k = tid >> 7;
        unsigned r[2];
        #pragma unroll
        for (int j = 0; j < 2; ++j) {
            const int f0 = k * 16 + (lane & 3) * 2 + j * 8;
            const int h  = n * 8 + (lane >> 2);
            r[j] = pack_bf2(w_deep[f0 * HDIM + h], w_deep[(f0 + 1) * HDIM + h]);
        }
        g_wdfrag[tid] = make_uint2(r[0], r[1]);
    }

    // w_ffn(deep) bf16, deep C-fragment layout (zero-padded beyond TS)
    if (tid < MT * NT_DP * 32) {
        const int n = (tid >> 5) % NT_DP;
        const int m = tid / (NT_DP * 32);
        const int t0 = m * 16 + (lane >> 2);
        const int h  = n * 8 + (lane & 3) * 2;
        float w0 = 0.f, w1 = 0.f, w2 = 0.f, w3 = 0.f;
        if (t0 < TS)     { w0 = w_ffn[t0 * HDIM + h];       w1 = w_ffn[t0 * HDIM + h + 1]; }
        if (t0 + 8 < TS) { w2 = w_ffn[(t0 + 8) * HDIM + h]; w3 = w_ffn[(t0 + 8) * HDIM + h + 1]; }
        g_wffndbf[tid] = make_uint2(pack_bf2(w0, w1), pack_bf2(w2, w3));
    }

    // b_deep in deep C-frag layout
    if (tid < NT_DP * 32) {
        const int n = tid >> 5;
        const int h = n * 8 + (lane & 3) * 2;
        g_bdfrag[tid] = make_float2(b_deep[h], b_deep[h + 1]);
    }
}

__device__ __forceinline__ void mma_bf16(float* c,
                                         unsigned a0, unsigned a1, unsigned a2, unsigned a3,
                                         unsigned b0, unsigned b1)
{
    asm volatile("mma.sync.aligned.m16n8k16.row.col.f32.bf16.bf16.f32 "
                 "{%0,%1,%2,%3}, {%4,%5,%6,%7}, {%8,%9}, {%0,%1,%2,%3};"
                 : "+f"(c[0]), "+f"(c[1]), "+f"(c[2]), "+f"(c[3])
                 : "r"(a0), "r"(a1), "r"(a2), "r"(a3), "r"(b0), "r"(b1));
}
__device__ __forceinline__ void ldsm_x4(unsigned& r0, unsigned& r1, unsigned& r2, unsigned& r3,
                                        unsigned addr)
{
    asm volatile("ldmatrix.sync.aligned.m8n8.x4.shared.b16 {%0,%1,%2,%3}, [%4];"
                 : "=r"(r0), "=r"(r1), "=r"(r2), "=r"(r3) : "r"(addr));
}

// deep GEMM for m-tile `d`: b-frags shared across n, 4 independent acc chains.
__device__ __forceinline__ void deep_run(int d, unsigned ldsA, unsigned MROW,
                                         int lane, float& partial)
{
    float acc[NT_DP][4];
    #pragma unroll
    for (int n = 0; n < NT_DP; ++n)
        #pragma unroll
        for (int p = 0; p < 4; ++p) acc[n][p] = 0.f;

    #pragma unroll
    for (int k = 0; k < KT_DP; ++k) {
        unsigned a0, a1, a2, a3;
        ldsm_x4(a0, a1, a2, a3, ldsA + d * MROW + k * 32);
        const uint2* bfp = g_wdfrag + k * NT_DP * 32 + lane;
        #pragma unroll
        for (int n = 0; n < NT_DP; ++n) {
            const uint2 bb = bfp[n * 32];
            mma_bf16(acc[n], a0, a1, a2, a3, bb.x, bb.y);
        }
    }
    #pragma unroll
    for (int n = 0; n < NT_DP; ++n) {
        const float2 bd = g_bdfrag[n * 32 + lane];
        const uint2 wq = g_wffndbf[(d * NT_DP + n) * 32 + lane];
        const float2 f0 = bf2f(wq.x), f1 = bf2f(wq.y);
        partial += fmaxf(acc[n][0] + bd.x, 0.f) * f0.x
                 + fmaxf(acc[n][1] + bd.y, 0.f) * f0.y
                 + fmaxf(acc[n][2] + bd.x, 0.f) * f1.x
                 + fmaxf(acc[n][3] + bd.y, 0.f) * f1.y;
    }
}

__global__ __launch_bounds__(NTHREADS, 4)
void deepfm_mma_kernel(const int* __restrict__ x,
                       const float* __restrict__ emb,
                       const float* __restrict__ b_ffn,
                       float* __restrict__ out)
{
    __shared__ __align__(16) __nv_bfloat16 sEb[SPC * 112 * EB_STRIDE];  // 32.3 KB
    __shared__ int   tok[SPC * TS];
    __shared__ float red[NWARPS][SPC];

    const int b0   = blockIdx.x * SPC;
    const int tid  = threadIdx.x;
    const int lane = tid & 31;
    const int wid  = tid >> 5;

    // ---- tokens (both samples) + zero pad rows (100..111) x2 ----
    if (tid < SPC * TS) tok[tid] = x[b0 * TS + tid];
    if (tid < SPC * 12 * 9) {
        const int s  = tid / 108;
        const int rr = tid % 108;
        const int r  = 100 + rr / 9;
        const int q  = rr % 9;
        *reinterpret_cast<uint4*>(sEb + s * 112 * EB_STRIDE + r * EB_STRIDE + q * 8) =
            make_uint4(0, 0, 0, 0);
    }
    __syncthreads();

    float partial[SPC] = {0.f, 0.f};

    // ---- gather + bf16 convert + WIDE term: idx-outer, both samples inner ----
    #pragma unroll 2
    for (int idx = tid; idx < TS * 16; idx += NTHREADS) {
        const int t  = idx >> 4;
        const int fq = idx & 15;
        const uint2  wv = g_wwidebf[idx];
        const float2 f0 = bf2f(wv.x), f1 = bf2f(wv.y);
        const float4 v0 = *(const float4*)(emb + (long)tok[t] * FDIM + fq * 4);
        const float4 v1 = *(const float4*)(emb + (long)tok[TS + t] * FDIM + fq * 4);
        partial[0] += v0.x * f0.x + v0.y * f0.y + v0.z * f1.x + v0.w * f1.y;
        partial[1] += v1.x * f0.x + v1.y * f0.y + v1.z * f1.x + v1.w * f1.y;
        *reinterpret_cast<uint2*>(sEb + t * EB_STRIDE + fq * 4) =
            make_uint2(pack_bf2(v0.x, v0.y), pack_bf2(v0.z, v0.w));
        *reinterpret_cast<uint2*>(sEb + 112 * EB_STRIDE + t * EB_STRIDE + fq * 4) =
            make_uint2(pack_bf2(v1.x, v1.y), pack_bf2(v1.z, v1.w));
    }
    __syncthreads();

    // ldmatrix bases (g = lane>>3 selects 8x8 sub-matrix role)
    const int g = lane >> 3, r8 = lane & 7;
    const unsigned ldsA0 =
        smem_u32(sEb + ((g & 1) * 8 + r8) * EB_STRIDE + (g >> 1) * 8);
    const unsigned ldsB0 =
        smem_u32(sEb + ((g >> 1) * 8 + r8) * EB_STRIDE + (g & 1) * 8);
    const unsigned MROW = 16 * EB_STRIDE * 2;  // bytes per 16-row tile

    #pragma unroll
    for (int s = 0; s < SPC; ++s) {
        const unsigned ldsA = ldsA0 + s * SAMPLE_B;
        const unsigned ldsB = ldsB0 + s * SAMPLE_B;

        // ===== fm: balanced 4 blocks/warp; A-cache reloaded on row change =====
        {
            uint4 ak[KT_FM];
            int cur_mi = -1;
            #pragma unroll
            for (int j = 0; j < 4; ++j) {
                const int mi = BLK_MI[wid][j];
                const int mj = BLK_MJ[wid][j];
                if (mi != cur_mi) {
                    #pragma unroll
                    for (int k = 0; k < KT_FM; ++k)
                        ldsm_x4(ak[k].x, ak[k].y, ak[k].z, ak[k].w,
                                ldsA + mi * MROW + k * 32);
                    cur_mi = mi;
                }
                // k-split even/odd accumulator chains for ILP
                float accE[2][4], accO[2][4];
                #pragma unroll
                for (int n = 0; n < 2; ++n)
                    #pragma unroll
                    for (int q = 0; q < 4; ++q) { accE[n][q] = 0.f; accO[n][q] = 0.f; }

                #pragma unroll
                for (int k = 0; k < KT_FM; k += 2) {
                    unsigned b0r, b1r, b2r, b3r, c0, c1, c2, c3;
                    ldsm_x4(b0r, b1r, b2r, b3r, ldsB + mj * MROW + k * 32);
                    ldsm_x4(c0, c1, c2, c3, ldsB + mj * MROW + (k + 1) * 32);
                    mma_bf16(accE[0], ak[k].x, ak[k].y, ak[k].z, ak[k].w, b0r, b1r);
                    mma_bf16(accE[1], ak[k].x, ak[k].y, ak[k].z, ak[k].w, b2r, b3r);
                    mma_bf16(accO[0], ak[k+1].x, ak[k+1].y, ak[k+1].z, ak[k+1].w, c0, c1);
                    mma_bf16(accO[1], ak[k+1].x, ak[k+1].y, ak[k+1].z, ak[k+1].w, c2, c3);
                }
                const uint4 wp = g_wpairbf[(int)BLK_ID[wid][j] * 32 + lane];
                const float2 f0 = bf2f(wp.x), f1 = bf2f(wp.y);
                const float2 f2 = bf2f(wp.z), f3 = bf2f(wp.w);
                partial[s] += (accE[0][0] + accO[0][0]) * f0.x
                            + (accE[0][1] + accO[0][1]) * f0.y
                            + (accE[0][2] + accO[0][2]) * f1.x
                            + (accE[0][3] + accO[0][3]) * f1.y
                            + (accE[1][0] + accO[1][0]) * f2.x
                            + (accE[1][1] + accO[1][1]) * f2.y
                            + (accE[1][2] + accO[1][2]) * f3.x
                            + (accE[1][3] + accO[1][3]) * f3.y;
            }
        }

        // ===== deep: exactly one m-tile per warp =====
        deep_run(wid, ldsA, MROW, lane, partial[s]);
    }

    // ---- block reduce + sigmoid (both samples) ----
    #pragma unroll
    for (int s = 0; s < SPC; ++s) {
        float v = partial[s];
        #pragma unroll
        for (int off = 16; off; off >>= 1)
            v += __shfl_xor_sync(0xffffffffu, v, off);
        if (lane == 0) red[wid][s] = v;
    }
    __syncthreads();
    if (tid < SPC) {
        float total = 0.f;
        #pragma unroll
        for (int w = 0; w < NWARPS; ++w) total += red[w][tid];
        total += b_ffn[0];
        out[b0 + tid] = 1.f / (1.f + expf(-total));
    }
}

extern "C" void kernel_launch(void* const* d_in, const int* in_sizes, int n_in,
                              void* d_out, int out_size) {
    const int*   x      = (const int*)d_in[0];
    const float* emb    = (const float*)d_in[1];
    const float* w_deep = (const float*)d_in[2];
    const float* b_deep = (const float*)d_in[3];
    const float* w_ffn  = (const float*)d_in[4];
    const float* b_ffn  = (const float*)d_in[5];
    float* out = (float*)d_out;

    build_consts<<<13, 256>>>(w_deep, b_deep, w_ffn);
    deepfm_mma_kernel<<<8192 / SPC, NTHREADS>>>(x, emb, b_ffn, out);
}

// round 16
// speedup vs baseline: 1.4702x; 1.4702x over previous
#include <cuda_runtime.h>
#include <cuda_bf16.h>

#define TS       100
#define FDIM     64
#define HDIM     32
#define DEEP_N   3200            // TS * HDIM
#define WIDE_OFF 8150            // DEEP_N + NPAIR(4950)
#define NTHREADS 224
#define NWARPS   7
#define SPC      2               // samples per CTA

#define MT    7                  // m16 tiles covering 112 >= 100 rows
#define KT_FM 4                  // k16 tiles over f (Gram: k = feature dim)
#define NBLK  28                 // upper-tri 16x16 S-blocks (7*8/2)
#define KT_DP 4                  // k16 tiles covering 64 (deep)
#define NT_DP 4                  // n8 tiles covering 32 (deep)

#define EB_STRIDE 72             // halves per row; 144B -> conflict-free ldmatrix
#define SAMPLE_B  (112 * EB_STRIDE * 2)   // bytes per sample tile (16128)

// ---- batch-invariant fragment-major constants (rebuilt each launch) ----
__device__ uint4  g_wpairbf[NBLK * 32];          // pair weights, bf16, S C-frag layout
__device__ uint2  g_wdfrag[KT_DP * NT_DP * 32];  // w_deep bf16 b-frags
__device__ uint2  g_wffndbf[MT * NT_DP * 32];    // w_ffn(deep) bf16, deep C-frag layout
__device__ float2 g_bdfrag[NT_DP * 32];          // b_deep in deep C-frag layout
__device__ __align__(16) uint2 g_wwidebf[TS * FDIM / 4];  // wide weights bf16

__device__ __forceinline__ unsigned pack_bf2(float lo, float hi) {
    __nv_bfloat162 h = __floats2bfloat162_rn(lo, hi);
    return *reinterpret_cast<unsigned*>(&h);
}
__device__ __forceinline__ float2 bf2f(unsigned u) {
    return __bfloat1622float2(*reinterpret_cast<__nv_bfloat162*>(&u));
}
__device__ __forceinline__ unsigned smem_u32(const void* p) {
    return (unsigned)__cvta_generic_to_shared(p);
}
__device__ __forceinline__ float pairw(const float* w_ffn, int t, int tp) {
    if (t < TS && tp < TS && t < tp)
        return w_ffn[DEEP_N + t * (2 * TS - t - 1) / 2 + (tp - t - 1)];
    return 0.f;
}

__global__ void build_consts(const float* __restrict__ w_deep,
                             const float* __restrict__ b_deep,
                             const float* __restrict__ w_ffn)
{
    const int tid  = blockIdx.x * blockDim.x + threadIdx.x;
    const int lane = tid & 31;

    // wide weights -> bf16 pairs (source is only float2-aligned)
    if (tid < TS * FDIM / 4) {
        const float2 a = *(const float2*)(w_ffn + WIDE_OFF + tid * 4);
        const float2 c = *(const float2*)(w_ffn + WIDE_OFF + tid * 4 + 2);
        g_wwidebf[tid] = make_uint2(pack_bf2(a.x, a.y), pack_bf2(c.x, c.y));
    }

    // pair-weight bf16 fragments for S = E E^T blocks (upper-tri, incl. diagonal)
    if (tid < NBLK * 32) {
        const int blk = tid >> 5;
        int mi = 0, rem = blk;
        while (rem >= MT - mi) { rem -= MT - mi; ++mi; }
        const int mj = mi + rem;
        const int t  = mi * 16 + (lane >> 2);
        const int tp = mj * 16 + (lane & 3) * 2;
        g_wpairbf[tid] = make_uint4(
            pack_bf2(pairw(w_ffn, t,     tp),     pairw(w_ffn, t,     tp + 1)),
            pack_bf2(pairw(w_ffn, t + 8, tp),     pairw(w_ffn, t + 8, tp + 1)),
            pack_bf2(pairw(w_ffn, t,     tp + 8), pairw(w_ffn, t,     tp + 9)),
            pack_bf2(pairw(w_ffn, t + 8, tp + 8), pairw(w_ffn, t + 8, tp + 9)));
    }

    // w_deep b-fragments
    if (tid < KT_DP * NT_DP * 32) {
        const int n = (tid >> 5) & 3;
        const int k = tid >> 7;
        unsigned r[2];
        #pragma unroll
        for (int j = 0; j < 2; ++j) {
            const int f0 = k * 16 + (lane & 3) * 2 + j * 8;
            const int h  = n * 8 + (lane >> 2);
            r[j] = pack_bf2(w_deep[f0 * HDIM + h], w_deep[(f0 + 1) * HDIM + h]);
        }
        g_wdfrag[tid] = make_uint2(r[0], r[1]);
    }

    // w_ffn(deep) bf16, deep C-fragment layout (zero-padded beyond TS)
    if (tid < MT * NT_DP * 32) {
        const int n = (tid >> 5) % NT_DP;
        const int m = tid / (NT_DP * 32);
        const int t0 = m * 16 + (lane >> 2);
        const int h  = n * 8 + (lane & 3) * 2;
        float w0 = 0.f, w1 = 0.f, w2 = 0.f, w3 = 0.f;
        if (t0 < TS)     { w0 = w_ffn[t0 * HDIM + h];       w1 = w_ffn[t0 * HDIM + h + 1]; }
        if (t0 + 8 < TS) { w2 = w_ffn[(t0 + 8) * HDIM + h]; w3 = w_ffn[(t0 + 8) * HDIM + h + 1]; }
        g_wffndbf[tid] = make_uint2(pack_bf2(w0, w1), pack_bf2(w2, w3));
    }

    // b_deep in deep C-frag layout
    if (tid < NT_DP * 32) {
        const int n = tid >> 5;
        const int h = n * 8 + (lane & 3) * 2;
        g_bdfrag[tid] = make_float2(b_deep[h], b_deep[h + 1]);
    }
}

__device__ __forceinline__ void mma_bf16(float* c,
                                         unsigned a0, unsigned a1, unsigned a2, unsigned a3,
                                         unsigned b0, unsigned b1)
{
    asm volatile("mma.sync.aligned.m16n8k16.row.col.f32.bf16.bf16.f32 "
                 "{%0,%1,%2,%3}, {%4,%5,%6,%7}, {%8,%9}, {%0,%1,%2,%3};"
                 : "+f"(c[0]), "+f"(c[1]), "+f"(c[2]), "+f"(c[3])
                 : "r"(a0), "r"(a1), "r"(a2), "r"(a3), "r"(b0), "r"(b1));
}
__device__ __forceinline__ void ldsm_x4(unsigned& r0, unsigned& r1, unsigned& r2, unsigned& r3,
                                        unsigned addr)
{
    asm volatile("ldmatrix.sync.aligned.m8n8.x4.shared.b16 {%0,%1,%2,%3}, [%4];"
                 : "=r"(r0), "=r"(r1), "=r"(r2), "=r"(r3) : "r"(addr));
}

// fm for CNT consecutive S-blocks (MI, MJS..MJS+CNT-1): A-frags loaded once,
// paired mj blocks for ILP, all indices compile-time (no spills).
template <int MI, int MJS, int CNT>
__device__ __forceinline__ void fm_row(unsigned ldsA, unsigned ldsB, unsigned MROW,
                                       int lane, float& partial)
{
    constexpr int BASE = MI * MT - (MI * (MI - 1)) / 2 - MI;  // blk id = BASE + mj
    uint4 ak[KT_FM];
    #pragma unroll
    for (int k = 0; k < KT_FM; ++k)
        ldsm_x4(ak[k].x, ak[k].y, ak[k].z, ak[k].w, ldsA + MI * MROW + k * 32);

    // paired blocks
    #pragma unroll
    for (int p = 0; p < CNT / 2; ++p) {
        constexpr_pair_body:;
        const int mj = MJS + 2 * p;
        float acc[4][4];
        #pragma unroll
        for (int n = 0; n < 4; ++n)
            #pragma unroll
            for (int q = 0; q < 4; ++q) acc[n][q] = 0.f;

        #pragma unroll
        for (int k = 0; k < KT_FM; ++k) {
            unsigned b0r, b1r, b2r, b3r, c0, c1, c2, c3;
            ldsm_x4(b0r, b1r, b2r, b3r, ldsB + mj * MROW + k * 32);
            ldsm_x4(c0, c1, c2, c3, ldsB + (mj + 1) * MROW + k * 32);
            mma_bf16(acc[0], ak[k].x, ak[k].y, ak[k].z, ak[k].w, b0r, b1r);
            mma_bf16(acc[1], ak[k].x, ak[k].y, ak[k].z, ak[k].w, b2r, b3r);
            mma_bf16(acc[2], ak[k].x, ak[k].y, ak[k].z, ak[k].w, c0, c1);
            mma_bf16(acc[3], ak[k].x, ak[k].y, ak[k].z, ak[k].w, c2, c3);
        }
        {
            const uint4 wp = g_wpairbf[(BASE + mj) * 32 + lane];
            const float2 f0 = bf2f(wp.x), f1 = bf2f(wp.y);
            const float2 f2 = bf2f(wp.z), f3 = bf2f(wp.w);
            partial += acc[0][0] * f0.x + acc[0][1] * f0.y
                     + acc[0][2] * f1.x + acc[0][3] * f1.y
                     + acc[1][0] * f2.x + acc[1][1] * f2.y
                     + acc[1][2] * f3.x + acc[1][3] * f3.y;
        }
        {
            const uint4 wp = g_wpairbf[(BASE + mj + 1) * 32 + lane];
            const float2 f0 = bf2f(wp.x), f1 = bf2f(wp.y);
            const float2 f2 = bf2f(wp.z), f3 = bf2f(wp.w);
            partial += acc[2][0] * f0.x + acc[2][1] * f0.y
                     + acc[2][2] * f1.x + acc[2][3] * f1.y
                     + acc[3][0] * f2.x + acc[3][1] * f2.y
                     + acc[3][2] * f3.x + acc[3][3] * f3.y;
        }
    }
    // tail block
    if (CNT & 1) {
        const int mj = MJS + (CNT & ~1);
        float acc[2][4];
        #pragma unroll
        for (int n = 0; n < 2; ++n)
            #pragma unroll
            for (int q = 0; q < 4; ++q) acc[n][q] = 0.f;

        #pragma unroll
        for (int k = 0; k < KT_FM; ++k) {
            unsigned b0r, b1r, b2r, b3r;
            ldsm_x4(b0r, b1r, b2r, b3r, ldsB + mj * MROW + k * 32);
            mma_bf16(acc[0], ak[k].x, ak[k].y, ak[k].z, ak[k].w, b0r, b1r);
            mma_bf16(acc[1], ak[k].x, ak[k].y, ak[k].z, ak[k].w, b2r, b3r);
        }
        const uint4 wp = g_wpairbf[(BASE + mj) * 32 + lane];
        const float2 f0 = bf2f(wp.x), f1 = bf2f(wp.y);
        const float2 f2 = bf2f(wp.z), f3 = bf2f(wp.w);
        partial += acc[0][0] * f0.x + acc[0][1] * f0.y
                 + acc[0][2] * f1.x + acc[0][3] * f1.y
                 + acc[1][0] * f2.x + acc[1][1] * f2.y
                 + acc[1][2] * f3.x + acc[1][3] * f3.y;
    }
}

// deep GEMM for m-tile `d`
__device__ __forceinline__ void deep_run(int d, unsigned ldsA, unsigned MROW,
                                         int lane, float& partial)
{
    float acc[NT_DP][4];
    #pragma unroll
    for (int n = 0; n < NT_DP; ++n)
        #pragma unroll
        for (int p = 0; p < 4; ++p) acc[n][p] = 0.f;

    #pragma unroll
    for (int k = 0; k < KT_DP; ++k) {
        unsigned a0, a1, a2, a3;
        ldsm_x4(a0, a1, a2, a3, ldsA + d * MROW + k * 32);
        const uint2* bfp = g_wdfrag + k * NT_DP * 32 + lane;
        #pragma unroll
        for (int n = 0; n < NT_DP; ++n) {
            const uint2 bb = bfp[n * 32];
            mma_bf16(acc[n], a0, a1, a2, a3, bb.x, bb.y);
        }
    }
    #pragma unroll
    for (int n = 0; n < NT_DP; ++n) {
        const float2 bd = g_bdfrag[n * 32 + lane];
        const uint2 wq = g_wffndbf[(d * NT_DP + n) * 32 + lane];
        const float2 f0 = bf2f(wq.x), f1 = bf2f(wq.y);
        partial += fmaxf(acc[n][0] + bd.x, 0.f) * f0.x
                 + fmaxf(acc[n][1] + bd.y, 0.f) * f0.y
                 + fmaxf(acc[n][2] + bd.x, 0.f) * f1.x
                 + fmaxf(acc[n][3] + bd.y, 0.f) * f1.y;
    }
}

__global__ __launch_bounds__(NTHREADS, 4)
void deepfm_mma_kernel(const int* __restrict__ x,
                       const float* __restrict__ emb,
                       const float* __restrict__ b_ffn,
                       float* __restrict__ out)
{
    __shared__ __align__(16) __nv_bfloat16 sEb[SPC * 112 * EB_STRIDE];  // 32.3 KB
    __shared__ int   tok[SPC * TS];
    __shared__ float red[NWARPS][SPC];

    const int b0   = blockIdx.x * SPC;
    const int tid  = threadIdx.x;
    const int lane = tid & 31;
    const int wid  = tid >> 5;

    // ---- tokens (both samples) + zero pad rows (100..111) x2 ----
    if (tid < SPC * TS) tok[tid] = x[b0 * TS + tid];
    if (tid < SPC * 12 * 9) {
        const int s  = tid / 108;
        const int rr = tid % 108;
        const int r  = 100 + rr / 9;
        const int q  = rr % 9;
        *reinterpret_cast<uint4*>(sEb + s * 112 * EB_STRIDE + r * EB_STRIDE + q * 8) =
            make_uint4(0, 0, 0, 0);
    }
    __syncthreads();

    float partial[SPC] = {0.f, 0.f};

    // ---- gather + bf16 convert + WIDE term: idx-outer, both samples inner ----
    #pragma unroll 2
    for (int idx = tid; idx < TS * 16; idx += NTHREADS) {
        const int t  = idx >> 4;
        const int fq = idx & 15;
        const uint2  wv = g_wwidebf[idx];
        const float2 f0 = bf2f(wv.x), f1 = bf2f(wv.y);
        const float4 v0 = *(const float4*)(emb + (long)tok[t] * FDIM + fq * 4);
        const float4 v1 = *(const float4*)(emb + (long)tok[TS + t] * FDIM + fq * 4);
        partial[0] += v0.x * f0.x + v0.y * f0.y + v0.z * f1.x + v0.w * f1.y;
        partial[1] += v1.x * f0.x + v1.y * f0.y + v1.z * f1.x + v1.w * f1.y;
        *reinterpret_cast<uint2*>(sEb + t * EB_STRIDE + fq * 4) =
            make_uint2(pack_bf2(v0.x, v0.y), pack_bf2(v0.z, v0.w));
        *reinterpret_cast<uint2*>(sEb + 112 * EB_STRIDE + t * EB_STRIDE + fq * 4) =
            make_uint2(pack_bf2(v1.x, v1.y), pack_bf2(v1.z, v1.w));
    }
    __syncthreads();

    // ldmatrix bases (g = lane>>3 selects 8x8 sub-matrix role)
    const int g = lane >> 3, r8 = lane & 7;
    const unsigned ldsA0 =
        smem_u32(sEb + ((g & 1) * 8 + r8) * EB_STRIDE + (g >> 1) * 8);
    const unsigned ldsB0 =
        smem_u32(sEb + ((g >> 1) * 8 + r8) * EB_STRIDE + (g & 1) * 8);
    const unsigned MROW = 16 * EB_STRIDE * 2;  // bytes per 16-row tile

    #pragma unroll
    for (int s = 0; s < SPC; ++s) {
        const unsigned ldsA = ldsA0 + s * SAMPLE_B;
        const unsigned ldsB = ldsB0 + s * SAMPLE_B;

        // ===== fm: balanced static schedule, 4 blocks per warp =====
        if      (wid == 0) fm_row<0, 0, 4>(ldsA, ldsB, MROW, lane, partial[s]);
        else if (wid == 1) fm_row<1, 1, 4>(ldsA, ldsB, MROW, lane, partial[s]);
        else if (wid == 2) fm_row<2, 2, 4>(ldsA, ldsB, MROW, lane, partial[s]);
        else if (wid == 3) fm_row<3, 3, 4>(ldsA, ldsB, MROW, lane, partial[s]);
        else if (wid == 4) {
            fm_row<4, 4, 3>(ldsA, ldsB, MROW, lane, partial[s]);
            fm_row<2, 6, 1>(ldsA, ldsB, MROW, lane, partial[s]);
        } else if (wid == 5) {
            fm_row<5, 5, 2>(ldsA, ldsB, MROW, lane, partial[s]);
            fm_row<1, 5, 2>(ldsA, ldsB, MROW, lane, partial[s]);
        } else {
            fm_row<6, 6, 1>(ldsA, ldsB, MROW, lane, partial[s]);
            fm_row<0, 4, 3>(ldsA, ldsB, MROW, lane, partial[s]);
        }

        // ===== deep: exactly one m-tile per warp =====
        deep_run(wid, ldsA, MROW, lane, partial[s]);
    }

    // ---- block reduce + sigmoid (both samples) ----
    #pragma unroll
    for (int s = 0; s < SPC; ++s) {
        float v = partial[s];
        #pragma unroll
        for (int off = 16; off; off >>= 1)
            v += __shfl_xor_sync(0xffffffffu, v, off);
        if (lane == 0) red[wid][s] = v;
    }
    __syncthreads();
    if (tid < SPC) {
        float total = 0.f;
        #pragma unroll
        for (int w = 0; w < NWARPS; ++w) total += red[w][tid];
        total += b_ffn[0];
        out[b0 + tid] = 1.f / (1.f + expf(-total));
    }
}

extern "C" void kernel_launch(void* const* d_in, const int* in_sizes, int n_in,
                              void* d_out, int out_size) {
    const int*   x      = (const int*)d_in[0];
    const float* emb    = (const float*)d_in[1];
    const float* w_deep = (const float*)d_in[2];
    const float* b_deep = (const float*)d_in[3];
    const float* w_ffn  = (const float*)d_in[4];
    const float* b_ffn  = (const float*)d_in[5];
    float* out = (float*)d_out;

    build_consts<<<13, 256>>>(w_deep, b_deep, w_ffn);
    deepfm_mma_kernel<<<8192 / SPC, NTHREADS>>>(x, emb, b_ffn, out);
}

// round 17
// speedup vs baseline: 1.7401x; 1.1836x over previous
#include <cuda_runtime.h>
#include <cuda_bf16.h>

#define TS       100
#define FDIM     64
#define HDIM     32
#define DEEP_N   3200            // TS * HDIM
#define WIDE_OFF 8150            // DEEP_N + NPAIR(4950)
#define NTHREADS 224
#define NWARPS   7
#define SPC      2               // samples per CTA

#define MT    7                  // m16 tiles covering 112 >= 100 rows
#define KT_FM 4                  // k16 tiles over f (Gram: k = feature dim)
#define NBLK  28                 // upper-tri 16x16 S-blocks (7*8/2)
#define KT_DP 4                  // k16 tiles covering 64 (deep)
#define NT_DP 4                  // n8 tiles covering 32 (deep)

#define EB_STRIDE 72             // halves per row; 144B -> conflict-free ldmatrix
#define SAMPLE_B  (112 * EB_STRIDE * 2)   // bytes per sample tile (16128)

// ---- batch-invariant fragment-major constants (rebuilt each launch) ----
__device__ uint4  g_wpairbf[NBLK * 32];          // pair weights, bf16, S C-frag layout
__device__ uint2  g_wdfrag[KT_DP * NT_DP * 32];  // w_deep bf16 b-frags
__device__ uint2  g_wffndbf[MT * NT_DP * 32];    // w_ffn(deep) bf16, deep C-frag layout
__device__ float2 g_bdfrag[NT_DP * 32];          // b_deep in deep C-frag layout
__device__ __align__(16) uint2 g_wwidebf[TS * FDIM / 4];  // wide weights bf16

__constant__ int DEEP_CNT[NWARPS]   = {0, 0, 1, 1, 1, 2, 2};
__constant__ int DEEP_START[NWARPS] = {0, 0, 0, 1, 2, 3, 5};

__device__ __forceinline__ unsigned pack_bf2(float lo, float hi) {
    __nv_bfloat162 h = __floats2bfloat162_rn(lo, hi);
    return *reinterpret_cast<unsigned*>(&h);
}
__device__ __forceinline__ float2 bf2f(unsigned u) {
    return __bfloat1622float2(*reinterpret_cast<__nv_bfloat162*>(&u));
}
__device__ __forceinline__ unsigned smem_u32(const void* p) {
    return (unsigned)__cvta_generic_to_shared(p);
}
__device__ __forceinline__ float pairw(const float* w_ffn, int t, int tp) {
    if (t < TS && tp < TS && t < tp)
        return w_ffn[DEEP_N + t * (2 * TS - t - 1) / 2 + (tp - t - 1)];
    return 0.f;
}

__global__ void build_consts(const float* __restrict__ w_deep,
                             const float* __restrict__ b_deep,
                             const float* __restrict__ w_ffn)
{
    const int tid  = blockIdx.x * blockDim.x + threadIdx.x;
    const int lane = tid & 31;

    // wide weights -> bf16 pairs (source is only float2-aligned)
    if (tid < TS * FDIM / 4) {
        const float2 a = *(const float2*)(w_ffn + WIDE_OFF + tid * 4);
        const float2 c = *(const float2*)(w_ffn + WIDE_OFF + tid * 4 + 2);
        g_wwidebf[tid] = make_uint2(pack_bf2(a.x, a.y), pack_bf2(c.x, c.y));
    }

    // pair-weight bf16 fragments for S = E E^T blocks (upper-tri, incl. diagonal)
    if (tid < NBLK * 32) {
        const int blk = tid >> 5;
        int mi = 0, rem = blk;
        while (rem >= MT - mi) { rem -= MT - mi; ++mi; }
        const int mj = mi + rem;
        const int t  = mi * 16 + (lane >> 2);
        const int tp = mj * 16 + (lane & 3) * 2;
        g_wpairbf[tid] = make_uint4(
            pack_bf2(pairw(w_ffn, t,     tp),     pairw(w_ffn, t,     tp + 1)),
            pack_bf2(pairw(w_ffn, t + 8, tp),     pairw(w_ffn, t + 8, tp + 1)),
            pack_bf2(pairw(w_ffn, t,     tp + 8), pairw(w_ffn, t,     tp + 9)),
            pack_bf2(pairw(w_ffn, t + 8, tp + 8), pairw(w_ffn, t + 8, tp + 9)));
    }

    // w_deep b-fragments
    if (tid < KT_DP * NT_DP * 32) {
        const int n = (tid >> 5) & 3;
        const int k = tid >> 7;
        unsigned r[2];
        #pragma unroll
        for (int j = 0; j < 2; ++j) {
            const int f0 = k * 16 + (lane & 3) * 2 + j * 8;
            const int h  = n * 8 + (lane >> 2);
            r[j] = pack_bf2(w_deep[f0 * HDIM + h], w_deep[(f0 + 1) * HDIM + h]);
        }
        g_wdfrag[tid] = make_uint2(r[0], r[1]);
    }

    // w_ffn(deep) bf16, deep C-fragment layout (zero-padded beyond TS)
    if (tid < MT * NT_DP * 32) {
        const int n = (tid >> 5) % NT_DP;
        const int m = tid / (NT_DP * 32);
        const int t0 = m * 16 + (lane >> 2);
        const int h  = n * 8 + (lane & 3) * 2;
        float w0 = 0.f, w1 = 0.f, w2 = 0.f, w3 = 0.f;
        if (t0 < TS)     { w0 = w_ffn[t0 * HDIM + h];       w1 = w_ffn[t0 * HDIM + h + 1]; }
        if (t0 + 8 < TS) { w2 = w_ffn[(t0 + 8) * HDIM + h]; w3 = w_ffn[(t0 + 8) * HDIM + h + 1]; }
        g_wffndbf[tid] = make_uint2(pack_bf2(w0, w1), pack_bf2(w2, w3));
    }

    // b_deep in deep C-frag layout
    if (tid < NT_DP * 32) {
        const int n = tid >> 5;
        const int h = n * 8 + (lane & 3) * 2;
        g_bdfrag[tid] = make_float2(b_deep[h], b_deep[h + 1]);
    }
}

__device__ __forceinline__ void mma_bf16(float* c,
                                         unsigned a0, unsigned a1, unsigned a2, unsigned a3,
                                         unsigned b0, unsigned b1)
{
    asm volatile("mma.sync.aligned.m16n8k16.row.col.f32.bf16.bf16.f32 "
                 "{%0,%1,%2,%3}, {%4,%5,%6,%7}, {%8,%9}, {%0,%1,%2,%3};"
                 : "+f"(c[0]), "+f"(c[1]), "+f"(c[2]), "+f"(c[3])
                 : "r"(a0), "r"(a1), "r"(a2), "r"(a3), "r"(b0), "r"(b1));
}
__device__ __forceinline__ void ldsm_x4(unsigned& r0, unsigned& r1, unsigned& r2, unsigned& r3,
                                        unsigned addr)
{
    asm volatile("ldmatrix.sync.aligned.m8n8.x4.shared.b16 {%0,%1,%2,%3}, [%4];"
                 : "=r"(r0), "=r"(r1), "=r"(r2), "=r"(r3) : "r"(addr));
}

// deep GEMM for CNT m-tiles starting at `st`: w_deep b-frags loaded once per
// (k,n) and shared across the m-tiles; MMA streams interleave for ILP.
template <int CNT>
__device__ __forceinline__ void deep_run(int st, unsigned ldsA, unsigned MROW,
                                         int lane, float& partial)
{
    float acc[CNT][NT_DP][4];
    #pragma unroll
    for (int q = 0; q < CNT; ++q)
        #pragma unroll
        for (int n = 0; n < NT_DP; ++n)
            #pragma unroll
            for (int p = 0; p < 4; ++p) acc[q][n][p] = 0.f;

    #pragma unroll
    for (int k = 0; k < KT_DP; ++k) {
        unsigned a[CNT][4];
        #pragma unroll
        for (int q = 0; q < CNT; ++q)
            ldsm_x4(a[q][0], a[q][1], a[q][2], a[q][3],
                    ldsA + (st + q) * MROW + k * 32);
        const uint2* bfp = g_wdfrag + k * NT_DP * 32 + lane;
        #pragma unroll
        for (int n = 0; n < NT_DP; ++n) {
            const uint2 bb = bfp[n * 32];
            #pragma unroll
            for (int q = 0; q < CNT; ++q)
                mma_bf16(acc[q][n], a[q][0], a[q][1], a[q][2], a[q][3], bb.x, bb.y);
        }
    }
    #pragma unroll
    for (int q = 0; q < CNT; ++q) {
        const int d = st + q;
        #pragma unroll
        for (int n = 0; n < NT_DP; ++n) {
            const float2 bd = g_bdfrag[n * 32 + lane];
            const uint2 wq = g_wffndbf[(d * NT_DP + n) * 32 + lane];
            const float2 f0 = bf2f(wq.x), f1 = bf2f(wq.y);
            partial += fmaxf(acc[q][n][0] + bd.x, 0.f) * f0.x
                     + fmaxf(acc[q][n][1] + bd.y, 0.f) * f0.y
                     + fmaxf(acc[q][n][2] + bd.x, 0.f) * f1.x
                     + fmaxf(acc[q][n][3] + bd.y, 0.f) * f1.y;
        }
    }
}

__global__ __launch_bounds__(NTHREADS, 4)
void deepfm_mma_kernel(const int* __restrict__ x,
                       const float* __restrict__ emb,
                       const float* __restrict__ b_ffn,
                       float* __restrict__ out)
{
    __shared__ __align__(16) __nv_bfloat16 sEb[SPC * 112 * EB_STRIDE];  // 32.3 KB
    __shared__ float red[NWARPS][SPC];

    const int b0   = blockIdx.x * SPC;
    const int tid  = threadIdx.x;
    const int lane = tid & 31;
    const int wid  = tid >> 5;

    float partial[SPC] = {0.f, 0.f};

    // ---- fused gather + bf16 convert + pad-zero + WIDE term ----
    // 112*16 = 1792 = 8 * NTHREADS: exactly 8 iterations, fully unrolled.
    // Tokens read straight from global (L1-broadcast across the 16 lanes
    // sharing each t) - no smem staging, no prologue sync.
    #pragma unroll
    for (int ii = 0; ii < 8; ++ii) {
        const int idx = tid + ii * NTHREADS;
        const int t  = idx >> 4;
        const int fq = idx & 15;
        if (t < TS) {
            const int tk0 = __ldg(x + b0 * TS + t);
            const int tk1 = __ldg(x + b0 * TS + TS + t);
            const uint2  wv = g_wwidebf[idx];
            const float2 f0 = bf2f(wv.x), f1 = bf2f(wv.y);
            const float4 v0 = *(const float4*)(emb + (long)tk0 * FDIM + fq * 4);
            const float4 v1 = *(const float4*)(emb + (long)tk1 * FDIM + fq * 4);
            partial[0] += v0.x * f0.x + v0.y * f0.y + v0.z * f1.x + v0.w * f1.y;
            partial[1] += v1.x * f0.x + v1.y * f0.y + v1.z * f1.x + v1.w * f1.y;
            *reinterpret_cast<uint2*>(sEb + t * EB_STRIDE + fq * 4) =
                make_uint2(pack_bf2(v0.x, v0.y), pack_bf2(v0.z, v0.w));
            *reinterpret_cast<uint2*>(sEb + 112 * EB_STRIDE + t * EB_STRIDE + fq * 4) =
                make_uint2(pack_bf2(v1.x, v1.y), pack_bf2(v1.z, v1.w));
        } else {
            *reinterpret_cast<uint2*>(sEb + t * EB_STRIDE + fq * 4) = make_uint2(0, 0);
            *reinterpret_cast<uint2*>(sEb + 112 * EB_STRIDE + t * EB_STRIDE + fq * 4) =
                make_uint2(0, 0);
        }
    }
    __syncthreads();

    // ldmatrix bases (g = lane>>3 selects 8x8 sub-matrix role)
    const int g = lane >> 3, r8 = lane & 7;
    const unsigned ldsA0 =
        smem_u32(sEb + ((g & 1) * 8 + r8) * EB_STRIDE + (g >> 1) * 8);
    const unsigned ldsB0 =
        smem_u32(sEb + ((g >> 1) * 8 + r8) * EB_STRIDE + (g & 1) * 8);
    const unsigned MROW = 16 * EB_STRIDE * 2;  // bytes per 16-row tile

    #pragma unroll
    for (int s = 0; s < SPC; ++s) {
        const unsigned ldsA = ldsA0 + s * SAMPLE_B;
        const unsigned ldsB = ldsB0 + s * SAMPLE_B;

        // ============ fm: S = E E^T, upper-tri blocks of row `wid` ============
        {
            uint4 ak[KT_FM];
            #pragma unroll
            for (int k = 0; k < KT_FM; ++k)
                ldsm_x4(ak[k].x, ak[k].y, ak[k].z, ak[k].w, ldsA + wid * MROW + k * 32);

            const int base = wid * MT - (wid * (wid - 1)) / 2;  // triangle row prefix
            int mj = wid, blk = base;

            // paired blocks for cross-block ILP
            for (; mj + 1 < MT; mj += 2, blk += 2) {
                float acc[4][4];
                #pragma unroll
                for (int n = 0; n < 4; ++n)
                    #pragma unroll
                    for (int q = 0; q < 4; ++q) acc[n][q] = 0.f;

                #pragma unroll
                for (int k = 0; k < KT_FM; ++k) {
                    unsigned b0r, b1r, b2r, b3r, c0, c1, c2, c3;
                    ldsm_x4(b0r, b1r, b2r, b3r, ldsB + mj * MROW + k * 32);
                    ldsm_x4(c0, c1, c2, c3, ldsB + (mj + 1) * MROW + k * 32);
                    mma_bf16(acc[0], ak[k].x, ak[k].y, ak[k].z, ak[k].w, b0r, b1r);
                    mma_bf16(acc[1], ak[k].x, ak[k].y, ak[k].z, ak[k].w, b2r, b3r);
                    mma_bf16(acc[2], ak[k].x, ak[k].y, ak[k].z, ak[k].w, c0, c1);
                    mma_bf16(acc[3], ak[k].x, ak[k].y, ak[k].z, ak[k].w, c2, c3);
                }
                {
                    const uint4 wp = g_wpairbf[blk * 32 + lane];
                    const float2 f0 = bf2f(wp.x), f1 = bf2f(wp.y);
                    const float2 f2 = bf2f(wp.z), f3 = bf2f(wp.w);
                    partial[s] += acc[0][0] * f0.x + acc[0][1] * f0.y
                                + acc[0][2] * f1.x + acc[0][3] * f1.y
                                + acc[1][0] * f2.x + acc[1][1] * f2.y
                                + acc[1][2] * f3.x + acc[1][3] * f3.y;
                }
                {
                    const uint4 wp = g_wpairbf[(blk + 1) * 32 + lane];
                    const float2 f0 = bf2f(wp.x), f1 = bf2f(wp.y);
                    const float2 f2 = bf2f(wp.z), f3 = bf2f(wp.w);
                    partial[s] += acc[2][0] * f0.x + acc[2][1] * f0.y
                                + acc[2][2] * f1.x + acc[2][3] * f1.y
                                + acc[3][0] * f2.x + acc[3][1] * f2.y
                                + acc[3][2] * f3.x + acc[3][3] * f3.y;
                }
            }
            // tail block (rows with odd block count)
            if (mj < MT) {
                float acc[2][4];
                #pragma unroll
                for (int n = 0; n < 2; ++n)
                    #pragma unroll
                    for (int q = 0; q < 4; ++q) acc[n][q] = 0.f;

                #pragma unroll
                for (int k = 0; k < KT_FM; ++k) {
                    unsigned b0r, b1r, b2r, b3r;
                    ldsm_x4(b0r, b1r, b2r, b3r, ldsB + mj * MROW + k * 32);
                    mma_bf16(acc[0], ak[k].x, ak[k].y, ak[k].z, ak[k].w, b0r, b1r);
                    mma_bf16(acc[1], ak[k].x, ak[k].y, ak[k].z, ak[k].w, b2r, b3r);
                }
                const uint4 wp = g_wpairbf[blk * 32 + lane];
                const float2 f0 = bf2f(wp.x), f1 = bf2f(wp.y);
                const float2 f2 = bf2f(wp.z), f3 = bf2f(wp.w);
                partial[s] += acc[0][0] * f0.x + acc[0][1] * f0.y
                            + acc[0][2] * f1.x + acc[0][3] * f1.y
                            + acc[1][0] * f2.x + acc[1][1] * f2.y
                            + acc[1][2] * f3.x + acc[1][3] * f3.y;
            }
        }

        // ============ deep: assigned m-tiles, b-frags hoisted across m ============
        {
            const int cnt = DEEP_CNT[wid];
            const int st  = DEEP_START[wid];
            if (cnt == 1)      deep_run<1>(st, ldsA, MROW, lane, partial[s]);
            else if (cnt == 2) deep_run<2>(st, ldsA, MROW, lane, partial[s]);
        }
    }

    // ---- block reduce + sigmoid (both samples) ----
    #pragma unroll
    for (int s = 0; s < SPC; ++s) {
        float v = partial[s];
        #pragma unroll
        for (int off = 16; off; off >>= 1)
            v += __shfl_xor_sync(0xffffffffu, v, off);
        if (lane == 0) red[wid][s] = v;
    }
    __syncthreads();
    if (tid < SPC) {
        float total = 0.f;
        #pragma unroll
        for (int w = 0; w < NWARPS; ++w) total += red[w][tid];
        total += b_ffn[0];
        out[b0 + tid] = 1.f / (1.f + expf(-total));
    }
}

extern "C" void kernel_launch(void* const* d_in, const int* in_sizes, int n_in,
                              void* d_out, int out_size) {
    const int*   x      = (const int*)d_in[0];
    const float* emb    = (const float*)d_in[1];
    const float* w_deep = (const float*)d_in[2];
    const float* b_deep = (const float*)d_in[3];
    const float* w_ffn  = (const float*)d_in[4];
    const float* b_ffn  = (const float*)d_in[5];
    float* out = (float*)d_out;

    build_consts<<<13, 256>>>(w_deep, b_deep, w_ffn);
    deepfm_mma_kernel<<<8192 / SPC, NTHREADS>>>(x, emb, b_ffn, out);
}